// round 7
// baseline (speedup 1.0000x reference)
#include <cuda_runtime.h>
#include <cuda_bf16.h>
#include <math.h>
#include <cstdint>

#define N_CELLS 10000
#define P_GENES 8000
#define L_FAC   100
#define KP      112      // padded K in global bf16 operand arrays
#define KS      120      // smem row stride in halves (bank-conflict-free)
#define LAM_D   0.01
#define DELTA_F 0.001f

#define GRID_X  63                    // ceil(8000/128)
#define GRID_Y1 79                    // ceil(10000/128)
#define NPART1  (GRID_X * GRID_Y1)    // 4977
#define NTRI    (GRID_X * (GRID_X + 1) / 2)   // 2016 upper-triangle tiles

#define OPER_SMEM (2 * 128 * KS * 2)          // 61440 bytes operands
#define ADJT_SMEM (128 * 128)                 // 16384 bytes uint8 adj^T tile

// ---------------- device scratch ----------------
__device__ __align__(16) __nv_bfloat16 g_a_bf  [N_CELLS * KP];
__device__ __align__(16) __nv_bfloat16 g_thp_bf[P_GENES * KP];
__device__ __align__(16) __nv_bfloat16 g_th_bf [P_GENES * KP];
__device__ __align__(16) __nv_bfloat16 g_B_bf  [P_GENES * KP];
__device__ float  g_et[L_FAC * L_FAC];
__device__ double g_part1[5120];
__device__ double g_part2[2048];

// ---------------- streams/events for capture fork-join (created at load) --
static cudaStream_t g_s2;
static cudaEvent_t  g_evStart, g_evTh, g_evA, g_evM;
static const bool g_init_done = [](){
    cudaStreamCreateWithFlags(&g_s2, cudaStreamNonBlocking);
    cudaEventCreateWithFlags(&g_evStart, cudaEventDisableTiming);
    cudaEventCreateWithFlags(&g_evTh,    cudaEventDisableTiming);
    cudaEventCreateWithFlags(&g_evA,     cudaEventDisableTiming);
    cudaEventCreateWithFlags(&g_evM,     cudaEventDisableTiming);
    return true;
}();

__device__ __forceinline__ float sigmoidf_(float x) {
    return 1.0f / (1.0f + expf(-x));
}

// ---------------- et = 0.5*(sigmoid(eta)+sigmoid(eta)^T) ----------------
__global__ void et_kernel(const float* __restrict__ eta) {
    int idx = blockIdx.x * blockDim.x + threadIdx.x;
    if (idx >= L_FAC * L_FAC) return;
    int i = idx / L_FAC, j = idx % L_FAC;
    g_et[idx] = 0.5f * (sigmoidf_(eta[i * L_FAC + j]) + sigmoidf_(eta[j * L_FAC + i]));
}

// ---------------- a = exp(alpha), bf16, K-padded ----------------
__global__ void expa_kernel(const float* __restrict__ alpha) {
    int idx = blockIdx.x * blockDim.x + threadIdx.x;
    if (idx >= N_CELLS * KP) return;
    int row = idx / KP, k = idx % KP;
    float v = (k < L_FAC) ? expf(alpha[row * L_FAC + k]) : 0.0f;
    g_a_bf[idx] = __float2bfloat16(v);
}

// ---------------- per-gene: softmax, theta_, B = th@et ; 16 genes/block ----
__global__ void __launch_bounds__(256)
theta_kernel(const float* __restrict__ theta, const float* __restrict__ gs) {
    __shared__ float et_s[L_FAC * L_FAC];   // 40 KB
    __shared__ float th_s[16][L_FAC];       // 6.4 KB

    int tid = threadIdx.x;
    for (int i = tid; i < L_FAC * L_FAC; i += 256) et_s[i] = g_et[i];

    int warp = tid >> 5, lane = tid & 31;
    int rowl = warp * 2 + (lane >> 4);      // 0..15 local gene row
    int l16  = lane & 15;
    int gene = blockIdx.x * 16 + rowl;      // P divisible by 16

    float v[7];
    float mx = -1e30f;
    #pragma unroll
    for (int j = 0; j < 7; j++) {
        int idx = l16 + 16 * j;
        v[j] = (idx < L_FAC) ? theta[gene * L_FAC + idx] : -1e30f;
        mx = fmaxf(mx, v[j]);
    }
    #pragma unroll
    for (int off = 8; off > 0; off >>= 1)
        mx = fmaxf(mx, __shfl_xor_sync(0xffffffff, mx, off, 16));
    float sum = 0.0f;
    #pragma unroll
    for (int j = 0; j < 7; j++) {
        int idx = l16 + 16 * j;
        v[j] = (idx < L_FAC) ? expf(v[j] - mx) : 0.0f;
        sum += v[j];
    }
    #pragma unroll
    for (int off = 8; off > 0; off >>= 1)
        sum += __shfl_xor_sync(0xffffffff, sum, off, 16);
    float inv = 1.0f / sum;
    float gsc = sigmoidf_(gs[gene]) + DELTA_F;

    #pragma unroll
    for (int j = 0; j < 7; j++) {
        int idx = l16 + 16 * j;
        if (idx < L_FAC) {
            float th = v[j] * inv;
            th_s[rowl][idx] = th;
            g_th_bf [gene * KP + idx] = __float2bfloat16(th);
            g_thp_bf[gene * KP + idx] = __float2bfloat16(th * gsc);
        }
    }
    if (l16 < 12) {  // zero pads k=100..111
        g_th_bf [gene * KP + L_FAC + l16] = __float2bfloat16(0.0f);
        g_thp_bf[gene * KP + L_FAC + l16] = __float2bfloat16(0.0f);
        g_B_bf  [gene * KP + L_FAC + l16] = __float2bfloat16(0.0f);
    }
    __syncthreads();

    for (int idx = tid; idx < 16 * L_FAC; idx += 256) {
        int r = idx / L_FAC, c = idx % L_FAC;
        float acc = 0.0f;
        #pragma unroll 4
        for (int m = 0; m < L_FAC; m++)
            acc = fmaf(th_s[r][m], et_s[m * L_FAC + c], acc);
        g_B_bf[(blockIdx.x * 16 + r) * KP + c] = __float2bfloat16(acc);
    }
}

// =====================================================================
// bf16 mma.sync GEMM: 128x128 block tile, 512 thr (16 warps 4x4),
// warp tile 32x32, whole K panel (112) staged once, scalar LDS frags.
// =====================================================================
__device__ __forceinline__ void mma16816(float c[4], const unsigned a[4], const unsigned b[2]) {
    asm volatile(
        "mma.sync.aligned.m16n8k16.row.col.f32.bf16.bf16.f32 "
        "{%0,%1,%2,%3}, {%4,%5,%6,%7}, {%8,%9}, {%0,%1,%2,%3};"
        : "+f"(c[0]), "+f"(c[1]), "+f"(c[2]), "+f"(c[3])
        : "r"(a[0]), "r"(a[1]), "r"(a[2]), "r"(a[3]), "r"(b[0]), "r"(b[1]));
}

__device__ __forceinline__ void gemm_main(
    const __nv_bfloat16* __restrict__ Aglob, int Arows, int rowBase,
    const __nv_bfloat16* __restrict__ Bglob, int Brows, int colBase,
    float acc[2][4][4], char* smem, int tid)
{
    __nv_bfloat16* As = (__nv_bfloat16*)smem;
    __nv_bfloat16* Bs = As + 128 * KS;

    // stage A & B tiles: 128 rows x 14 uint4 each
    #pragma unroll
    for (int i = tid; i < 128 * 16; i += 512) {
        int r = i >> 4, c = i & 15;
        if (c < 14) {
            int gr = rowBase + r;
            uint4 val = make_uint4(0u, 0u, 0u, 0u);
            if (gr < Arows) val = *(const uint4*)(Aglob + (size_t)gr * KP + c * 8);
            *(uint4*)((char*)As + r * (KS * 2) + c * 16) = val;
        }
    }
    #pragma unroll
    for (int i = tid; i < 128 * 16; i += 512) {
        int r = i >> 4, c = i & 15;
        if (c < 14) {
            int gr = colBase + r;
            uint4 val = make_uint4(0u, 0u, 0u, 0u);
            if (gr < Brows) val = *(const uint4*)(Bglob + (size_t)gr * KP + c * 8);
            *(uint4*)((char*)Bs + r * (KS * 2) + c * 16) = val;
        }
    }
    __syncthreads();

    int lane = tid & 31, warp = tid >> 5;
    int wm = warp >> 2, wn = warp & 3;
    int rq = lane >> 2;            // 0..7
    int kp = (lane & 3) << 1;      // 0,2,4,6

    #pragma unroll
    for (int mi = 0; mi < 2; mi++)
        #pragma unroll
        for (int nj = 0; nj < 4; nj++)
            #pragma unroll
            for (int q = 0; q < 4; q++) acc[mi][nj][q] = 0.0f;

    #pragma unroll
    for (int ks = 0; ks < 7; ks++) {
        int k0 = ks * 16 + kp;
        unsigned aF[2][4], bF[4][2];
        #pragma unroll
        for (int mi = 0; mi < 2; mi++) {
            const __nv_bfloat16* p = As + (wm * 32 + mi * 16 + rq) * KS + k0;
            aF[mi][0] = *(const unsigned*)(p);
            aF[mi][1] = *(const unsigned*)(p + 8 * KS);
            aF[mi][2] = *(const unsigned*)(p + 8);
            aF[mi][3] = *(const unsigned*)(p + 8 * KS + 8);
        }
        #pragma unroll
        for (int nj = 0; nj < 4; nj++) {
            const __nv_bfloat16* p = Bs + (wn * 32 + nj * 8 + rq) * KS + k0;
            bF[nj][0] = *(const unsigned*)(p);
            bF[nj][1] = *(const unsigned*)(p + 8);
        }
        #pragma unroll
        for (int mi = 0; mi < 2; mi++)
            #pragma unroll
            for (int nj = 0; nj < 4; nj++)
                mma16816(acc[mi][nj], aF[mi], bF[nj]);
    }
}

__device__ __forceinline__ double block_reduce512(float lsum, int tid) {
    __shared__ float red[16];
    #pragma unroll
    for (int off = 16; off > 0; off >>= 1)
        lsum += __shfl_xor_sync(0xffffffff, lsum, off);
    if ((tid & 31) == 0) red[tid >> 5] = lsum;
    __syncthreads();
    double t = 0.0;
    if (tid == 0) {
        #pragma unroll
        for (int w = 0; w < 16; w++) t += (double)red[w];
    }
    return t;
}

// ---- recon kernel: C = a @ thp^T, epilogue xlogy(X,C) - C ----
__global__ void __launch_bounds__(512, 2)
recon_kernel(const float* __restrict__ X) {
    extern __shared__ char dsm[];
    int tid = threadIdx.x;
    int rowBase = blockIdx.y * 128;   // cells
    int colBase = blockIdx.x * 128;   // genes

    float acc[2][4][4];
    gemm_main(g_a_bf, N_CELLS, rowBase, g_thp_bf, P_GENES, colBase, acc, dsm, tid);

    int lane = tid & 31, warp = tid >> 5;
    int wm = warp >> 2, wn = warp & 3;
    int rq = lane >> 2, kp = (lane & 3) << 1;

    float lsum = 0.0f;
    #pragma unroll
    for (int mi = 0; mi < 2; mi++) {
        #pragma unroll
        for (int nj = 0; nj < 4; nj++) {
            int r = rowBase + wm * 32 + mi * 16 + rq;
            int c = colBase + wn * 32 + nj * 8 + kp;
            if (c < P_GENES) {
                if (r < N_CELLS) {
                    float2 x = *(const float2*)(X + (size_t)r * P_GENES + c);
                    float rec = acc[mi][nj][0];
                    lsum += ((x.x > 0.0f) ? x.x * __logf(rec) : 0.0f) - rec;
                    rec = acc[mi][nj][1];
                    lsum += ((x.y > 0.0f) ? x.y * __logf(rec) : 0.0f) - rec;
                }
                if (r + 8 < N_CELLS) {
                    float2 x = *(const float2*)(X + (size_t)(r + 8) * P_GENES + c);
                    float rec = acc[mi][nj][2];
                    lsum += ((x.x > 0.0f) ? x.x * __logf(rec) : 0.0f) - rec;
                    rec = acc[mi][nj][3];
                    lsum += ((x.y > 0.0f) ? x.y * __logf(rec) : 0.0f) - rec;
                }
            }
        }
    }
    double t = block_reduce512(lsum, tid);
    if (tid == 0) g_part1[blockIdx.y * gridDim.x + blockIdx.x] = t;
}

// ---- mat kernel (upper-triangle tiles): M = B @ th^T symmetric ----
__global__ void __launch_bounds__(512, 2)
mat_kernel(const float* __restrict__ adj,
           const float* __restrict__ kappa,
           const float* __restrict__ rho) {
    extern __shared__ char dsm[];
    unsigned char* adjT = (unsigned char*)(dsm + OPER_SMEM);
    int tid = threadIdx.x;

    // unrank upper-triangle linear index -> (by, bx), by <= bx
    int li = blockIdx.x;
    int by = (int)(63.5 - sqrt(63.5 * 63.5 - 2.0 * (double)li));
    if (by < 0) by = 0;
    while ((by + 1) * GRID_X - ((by + 1) * by) / 2 <= li) by++;
    while (by * GRID_X - (by * (by - 1)) / 2 > li) by--;
    int bx = by + (li - (by * GRID_X - (by * (by - 1)) / 2));
    int rowBase = by * 128;
    int colBase = bx * 128;
    bool offDiag = (by != bx);

    // stage adj^T tile (coalesced reads) BEFORE compute so DRAM overlaps MMA
    if (offDiag) {
        #pragma unroll
        for (int i = tid; i < 128 * 128; i += 512) {
            int cc = i >> 7, rr = i & 127;   // cc: local col (adj row), rr: local row
            int gr = colBase + cc, gc = rowBase + rr;
            float v = 0.0f;
            if (gr < P_GENES && gc < P_GENES) v = adj[(size_t)gr * P_GENES + gc];
            adjT[i] = (v > 0.5f) ? 1 : 0;
        }
    }

    float acc[2][4][4];
    gemm_main(g_B_bf, P_GENES, rowBase, g_th_bf, P_GENES, colBase, acc, dsm, tid);
    __syncthreads();   // adjT writes visible to all consumers

    float sk = sigmoidf_(kappa[0]);
    float sr = sigmoidf_(rho[0]);
    float Af = (1.0f - sr) * (1.0f - sk);
    float C2 = (1.0f - sr) * sk;
    float C3 = Af + sr;

    int lane = tid & 31, warp = tid >> 5;
    int wm = warp >> 2, wn = warp & 3;
    int rq = lane >> 2, kp = (lane & 3) << 1;

    float lsum = 0.0f;
    #pragma unroll
    for (int mi = 0; mi < 2; mi++) {
        #pragma unroll
        for (int nj = 0; nj < 4; nj++) {
            int lr0 = wm * 32 + mi * 16 + rq;
            int lc  = wn * 32 + nj * 8 + kp;
            int c   = colBase + lc;
            if (c < P_GENES) {
                #pragma unroll
                for (int half = 0; half < 2; half++) {
                    int lr = lr0 + half * 8;
                    int r  = rowBase + lr;
                    if (r < P_GENES) {
                        float m0 = acc[mi][nj][half * 2 + 0];
                        float m1 = acc[mi][nj][half * 2 + 1];
                        // direct: pair (r, c), (r, c+1)
                        float2 a2 = *(const float2*)(adj + (size_t)r * P_GENES + c);
                        float arg0 = (a2.x > 0.5f) ? fmaf(Af, m0, C2) : fmaf(-Af, m0, C3);
                        float arg1 = (a2.y > 0.5f) ? fmaf(Af, m1, C2) : fmaf(-Af, m1, C3);
                        if (r != c)     lsum += __logf(arg0);
                        if (r != c + 1) lsum += __logf(arg1);
                        // transposed: pair (c, r), (c+1, r) — M symmetric
                        if (offDiag) {
                            unsigned char t0 = adjT[lc * 128 + lr];
                            unsigned char t1 = adjT[(lc + 1) * 128 + lr];
                            float brg0 = t0 ? fmaf(Af, m0, C2) : fmaf(-Af, m0, C3);
                            float brg1 = t1 ? fmaf(Af, m1, C2) : fmaf(-Af, m1, C3);
                            lsum += __logf(brg0) + __logf(brg1);
                        }
                    }
                }
            }
        }
    }
    double t = block_reduce512(lsum, tid);
    if (tid == 0) g_part2[li] = t;
}

// ---------------- final reduction ----------------
__global__ void __launch_bounds__(256)
fin_kernel(float* out) {
    int tid = threadIdx.x;
    double s1 = 0.0, s2 = 0.0;
    for (int i = tid; i < NPART1; i += 256) s1 += g_part1[i];
    for (int i = tid; i < NTRI; i += 256) s2 += g_part2[i];
    #pragma unroll
    for (int off = 16; off > 0; off >>= 1) {
        s1 += __shfl_xor_sync(0xffffffff, s1, off);
        s2 += __shfl_xor_sync(0xffffffff, s2, off);
    }
    __shared__ double r1[8], r2[8];
    if ((tid & 31) == 0) { r1[tid >> 5] = s1; r2[tid >> 5] = s2; }
    __syncthreads();
    if (tid == 0) {
        double t1 = 0.0, t2 = 0.0;
        #pragma unroll
        for (int w = 0; w < 8; w++) { t1 += r1[w]; t2 += r2[w]; }
        out[0] = (float)(-(LAM_D * t1 + t2));
    }
}

// ---------------- launch (stream fork-join: recon || mat) ----------------
extern "C" void kernel_launch(void* const* d_in, const int* in_sizes, int n_in,
                              void* d_out, int out_size) {
    const float* X     = (const float*)d_in[0];
    const float* adj   = (const float*)d_in[1];
    // d_in[2] adj_1m, d_in[3] weights: derivable from binary adj, unused
    const float* theta = (const float*)d_in[4];
    const float* alpha = (const float*)d_in[5];
    const float* eta   = (const float*)d_in[6];
    const float* gs    = (const float*)d_in[7];
    const float* kappa = (const float*)d_in[8];
    const float* rho   = (const float*)d_in[9];
    float* out = (float*)d_out;

    cudaFuncSetAttribute(recon_kernel, cudaFuncAttributeMaxDynamicSharedMemorySize, OPER_SMEM);
    cudaFuncSetAttribute(mat_kernel,   cudaFuncAttributeMaxDynamicSharedMemorySize, OPER_SMEM + ADJT_SMEM);

    // fork s2 off the capture (default) stream
    cudaEventRecord(g_evStart, 0);
    cudaStreamWaitEvent(g_s2, g_evStart, 0);

    // s2: a = exp(alpha) (independent of theta path)
    expa_kernel<<<(N_CELLS * KP + 255) / 256, 256, 0, g_s2>>>(alpha);
    cudaEventRecord(g_evA, g_s2);

    // s0: et -> theta (produces g_th, g_thp, g_B)
    et_kernel<<<(L_FAC * L_FAC + 255) / 256, 256>>>(eta);
    theta_kernel<<<P_GENES / 16, 256>>>(theta, gs);
    cudaEventRecord(g_evTh, 0);

    // s2: mat needs theta outputs
    cudaStreamWaitEvent(g_s2, g_evTh, 0);
    mat_kernel<<<NTRI, 512, OPER_SMEM + ADJT_SMEM, g_s2>>>(adj, kappa, rho);
    cudaEventRecord(g_evM, g_s2);

    // s0: recon needs g_a (from s2) and theta outputs
    cudaStreamWaitEvent(0, g_evA, 0);
    dim3 gRecon(GRID_X, GRID_Y1);
    recon_kernel<<<gRecon, 512, OPER_SMEM>>>(X);

    // join: fin needs both partial arrays
    cudaStreamWaitEvent(0, g_evM, 0);
    fin_kernel<<<1, 256>>>(out);
}

// round 8
// speedup vs baseline: 1.0488x; 1.0488x over previous
#include <cuda_runtime.h>
#include <cuda_bf16.h>
#include <math.h>
#include <cstdint>

#define N_CELLS 10000
#define P_GENES 8000
#define L_FAC   100
#define KP      112
#define LAM_D   0.01
#define DELTA_F 0.001f

#define GRID_X  63                    // ceil(8000/128)
#define GRID_Y1 79                    // ceil(10000/128)
#define N_PADR  (GRID_Y1 * 128)       // 10112 padded rows (A layout, recon)
#define P_PADR  (GRID_X * 128)        // 8064 padded rows
#define NPART1  (GRID_X * GRID_Y1)    // 4977
#define NPART2  (GRID_X * GRID_X)     // 3969

// fragment-major panel: 128 rows x 112 k = 8 mblocks x 7 kblocks x 128 u32
#define PANEL_U32   (8 * 7 * 128)     // 7168 u32 = 28672 B
#define PANEL_UINT4 (PANEL_U32 / 4)   // 1792
#define FRAG_SMEM   (2 * PANEL_U32 * 4)  // 57344 B

// ---------------- device scratch (zero-initialized; pads stay 0) ---------
__device__ __align__(16) unsigned g_a_fr  [(N_PADR / 128) * PANEL_U32];  // A-layout
__device__ __align__(16) unsigned g_B_fr  [(P_PADR / 128) * PANEL_U32];  // A-layout
__device__ __align__(16) unsigned g_th_fr [(P_PADR / 128) * PANEL_U32];  // B-layout
__device__ __align__(16) unsigned g_thp_fr[(P_PADR / 128) * PANEL_U32];  // B-layout
__device__ float  g_et[L_FAC * L_FAC];
__device__ double g_part1[5120];
__device__ double g_part2[4096];

// ---------------- streams/events (created at load; capture-legal) --------
static cudaStream_t g_s2;
static cudaEvent_t  g_evStart, g_evTh, g_evA, g_evM;
static const bool g_init_done = [](){
    cudaStreamCreateWithFlags(&g_s2, cudaStreamNonBlocking);
    cudaEventCreateWithFlags(&g_evStart, cudaEventDisableTiming);
    cudaEventCreateWithFlags(&g_evTh,    cudaEventDisableTiming);
    cudaEventCreateWithFlags(&g_evA,     cudaEventDisableTiming);
    cudaEventCreateWithFlags(&g_evM,     cudaEventDisableTiming);
    return true;
}();

__device__ __forceinline__ float sigmoidf_(float x) {
    return 1.0f / (1.0f + expf(-x));
}

__device__ __forceinline__ unsigned pack_bf2(float a, float b) {
    __nv_bfloat162 h = __floats2bfloat162_rn(a, b);
    return *reinterpret_cast<unsigned*>(&h);
}

// A-layout address (u32 index) for element (row, k), k even pair base
__device__ __forceinline__ int a_off(int row, int kk) {
    int p  = row >> 7, rm = row & 127;
    int m8 = rm >> 4,  ri = rm & 15;
    int kb = kk >> 4;
    int lane = (ri & 7) * 4 + ((kk & 7) >> 1);
    int reg  = (ri >> 3) + 2 * ((kk & 15) >> 3);
    return ((p * 8 + m8) * 7 + kb) * 128 + lane * 4 + reg;
}
// B-layout address (u32 index) for element (n, k), k even pair base
__device__ __forceinline__ int b_off(int n, int kk) {
    int q  = n >> 7, nm = n & 127;
    int np4 = nm >> 4, ni = nm & 15, sub = ni >> 3;
    int kb = kk >> 4;
    int lane = (ni & 7) * 4 + ((kk & 7) >> 1);
    int reg  = ((kk & 15) >> 3) + 2 * sub;
    return ((q * 8 + np4) * 7 + kb) * 128 + lane * 4 + reg;
}

// ---------------- et ----------------
__global__ void et_kernel(const float* __restrict__ eta) {
    int idx = blockIdx.x * blockDim.x + threadIdx.x;
    if (idx >= L_FAC * L_FAC) return;
    int i = idx / L_FAC, j = idx % L_FAC;
    g_et[idx] = 0.5f * (sigmoidf_(eta[i * L_FAC + j]) + sigmoidf_(eta[j * L_FAC + i]));
}

// ---------------- a = exp(alpha) -> fragment-major A-layout --------------
__global__ void expa_kernel(const float* __restrict__ alpha) {
    int idx = blockIdx.x * blockDim.x + threadIdx.x;
    if (idx >= N_PADR * 56) return;
    int row = idx / 56, kk = (idx % 56) * 2;
    float e0 = 0.0f, e1 = 0.0f;
    if (row < N_CELLS) {
        if (kk < L_FAC)     e0 = expf(alpha[row * L_FAC + kk]);
        if (kk + 1 < L_FAC) e1 = expf(alpha[row * L_FAC + kk + 1]);
    }
    g_a_fr[a_off(row, kk)] = pack_bf2(e0, e1);
}

// ---------------- per-gene: softmax, theta_, B = th@et -------------------
__global__ void __launch_bounds__(256)
theta_kernel(const float* __restrict__ theta, const float* __restrict__ gs) {
    __shared__ float et_s[L_FAC * L_FAC];   // 40 KB
    __shared__ float th_s[16][L_FAC];       // 6.4 KB
    __shared__ float gsc_s[16];

    int tid = threadIdx.x;
    for (int i = tid; i < L_FAC * L_FAC; i += 256) et_s[i] = g_et[i];

    int warp = tid >> 5, lane = tid & 31;
    int rowl = warp * 2 + (lane >> 4);
    int l16  = lane & 15;
    int gene = blockIdx.x * 16 + rowl;

    float v[7];
    float mx = -1e30f;
    #pragma unroll
    for (int j = 0; j < 7; j++) {
        int idx = l16 + 16 * j;
        v[j] = (idx < L_FAC) ? theta[gene * L_FAC + idx] : -1e30f;
        mx = fmaxf(mx, v[j]);
    }
    #pragma unroll
    for (int off = 8; off > 0; off >>= 1)
        mx = fmaxf(mx, __shfl_xor_sync(0xffffffff, mx, off, 16));
    float sum = 0.0f;
    #pragma unroll
    for (int j = 0; j < 7; j++) {
        int idx = l16 + 16 * j;
        v[j] = (idx < L_FAC) ? expf(v[j] - mx) : 0.0f;
        sum += v[j];
    }
    #pragma unroll
    for (int off = 8; off > 0; off >>= 1)
        sum += __shfl_xor_sync(0xffffffff, sum, off, 16);
    float inv = 1.0f / sum;

    #pragma unroll
    for (int j = 0; j < 7; j++) {
        int idx = l16 + 16 * j;
        if (idx < L_FAC) th_s[rowl][idx] = v[j] * inv;
    }
    if (l16 == 0) gsc_s[rowl] = sigmoidf_(gs[gene]) + DELTA_F;
    __syncthreads();

    // write th / thp in B-layout (pairs along k)
    for (int idx = tid; idx < 16 * 56; idx += 256) {
        int r = idx / 56, kk = (idx % 56) * 2;
        int n = blockIdx.x * 16 + r;
        float t0 = (kk < L_FAC) ? th_s[r][kk] : 0.0f;
        float t1 = (kk + 1 < L_FAC) ? th_s[r][kk + 1] : 0.0f;
        float g = gsc_s[r];
        int off = b_off(n, kk);
        g_th_fr [off] = pack_bf2(t0, t1);
        g_thp_fr[off] = pack_bf2(t0 * g, t1 * g);
    }

    // B = th @ et, written in A-layout (pairs along k)
    for (int idx = tid; idx < 16 * 56; idx += 256) {
        int r = idx / 56, kk = (idx % 56) * 2;
        int row = blockIdx.x * 16 + r;
        float a0 = 0.0f, a1 = 0.0f;
        if (kk < L_FAC) {
            #pragma unroll 4
            for (int m = 0; m < L_FAC; m++) {
                float t = th_s[r][m];
                a0 = fmaf(t, et_s[m * L_FAC + kk], a0);
                if (kk + 1 < L_FAC) a1 = fmaf(t, et_s[m * L_FAC + kk + 1], a1);
            }
        }
        g_B_fr[a_off(row, kk)] = pack_bf2(a0, a1);
    }
}

// =====================================================================
// bf16 mma GEMM: 128x128 tile, 512 thr (16 warps 4x4), warp tile 32x32,
// fragment-major operands: 4 x LDS.128 per kstep per thread.
// =====================================================================
__device__ __forceinline__ void mma16816(float c[4], const unsigned a[4],
                                         unsigned b0, unsigned b1) {
    asm volatile(
        "mma.sync.aligned.m16n8k16.row.col.f32.bf16.bf16.f32 "
        "{%0,%1,%2,%3}, {%4,%5,%6,%7}, {%8,%9}, {%0,%1,%2,%3};"
        : "+f"(c[0]), "+f"(c[1]), "+f"(c[2]), "+f"(c[3])
        : "r"(a[0]), "r"(a[1]), "r"(a[2]), "r"(a[3]), "r"(b0), "r"(b1));
}

__device__ __forceinline__ void gemm_main(
    const unsigned* __restrict__ Apanels, int panelA,
    const unsigned* __restrict__ Bpanels, int panelB,
    float acc[2][4][4], char* smem, int tid)
{
    uint4* AsV = (uint4*)smem;
    uint4* BsV = AsV + PANEL_UINT4;
    const uint4* srcA = ((const uint4*)Apanels) + (size_t)panelA * PANEL_UINT4;
    const uint4* srcB = ((const uint4*)Bpanels) + (size_t)panelB * PANEL_UINT4;
    for (int i = tid; i < PANEL_UINT4; i += 512) AsV[i] = srcA[i];
    for (int i = tid; i < PANEL_UINT4; i += 512) BsV[i] = srcB[i];
    __syncthreads();

    int lane = tid & 31, warp = tid >> 5;
    int wm = warp >> 2, wn = warp & 3;

    const char* As = smem;
    const char* Bs = smem + PANEL_U32 * 4;
    int laneOff = lane * 16;

    #pragma unroll
    for (int mi = 0; mi < 2; mi++)
        #pragma unroll
        for (int nj = 0; nj < 4; nj++)
            #pragma unroll
            for (int q = 0; q < 4; q++) acc[mi][nj][q] = 0.0f;

    #pragma unroll
    for (int ks = 0; ks < 7; ks++) {
        uint4 vA0 = *(const uint4*)(As + ((2 * wm + 0) * 7 + ks) * 512 + laneOff);
        uint4 vA1 = *(const uint4*)(As + ((2 * wm + 1) * 7 + ks) * 512 + laneOff);
        uint4 vB0 = *(const uint4*)(Bs + ((2 * wn + 0) * 7 + ks) * 512 + laneOff);
        uint4 vB1 = *(const uint4*)(Bs + ((2 * wn + 1) * 7 + ks) * 512 + laneOff);
        unsigned a0[4] = {vA0.x, vA0.y, vA0.z, vA0.w};
        unsigned a1[4] = {vA1.x, vA1.y, vA1.z, vA1.w};
        mma16816(acc[0][0], a0, vB0.x, vB0.y);
        mma16816(acc[0][1], a0, vB0.z, vB0.w);
        mma16816(acc[0][2], a0, vB1.x, vB1.y);
        mma16816(acc[0][3], a0, vB1.z, vB1.w);
        mma16816(acc[1][0], a1, vB0.x, vB0.y);
        mma16816(acc[1][1], a1, vB0.z, vB0.w);
        mma16816(acc[1][2], a1, vB1.x, vB1.y);
        mma16816(acc[1][3], a1, vB1.z, vB1.w);
    }
}

__device__ __forceinline__ double block_reduce512(float lsum, int tid) {
    __shared__ float red[16];
    #pragma unroll
    for (int off = 16; off > 0; off >>= 1)
        lsum += __shfl_xor_sync(0xffffffff, lsum, off);
    if ((tid & 31) == 0) red[tid >> 5] = lsum;
    __syncthreads();
    double t = 0.0;
    if (tid == 0) {
        #pragma unroll
        for (int w = 0; w < 16; w++) t += (double)red[w];
    }
    return t;
}

// ---- recon: C = a @ thp^T, epilogue xlogy(X,C) - C ----
__global__ void __launch_bounds__(512, 2)
recon_kernel(const float* __restrict__ X) {
    extern __shared__ char dsm[];
    int tid = threadIdx.x;
    int rowBase = blockIdx.y * 128;
    int colBase = blockIdx.x * 128;

    float acc[2][4][4];
    gemm_main(g_a_fr, blockIdx.y, g_thp_fr, blockIdx.x, acc, dsm, tid);

    int lane = tid & 31, warp = tid >> 5;
    int wm = warp >> 2, wn = warp & 3;
    int rq = lane >> 2, kp = (lane & 3) << 1;

    float lsum = 0.0f;
    #pragma unroll
    for (int mi = 0; mi < 2; mi++) {
        #pragma unroll
        for (int nj = 0; nj < 4; nj++) {
            int r = rowBase + wm * 32 + mi * 16 + rq;
            int c = colBase + wn * 32 + nj * 8 + kp;
            if (c < P_GENES) {
                if (r < N_CELLS) {
                    float2 x = *(const float2*)(X + (size_t)r * P_GENES + c);
                    float rec = acc[mi][nj][0];
                    lsum += ((x.x > 0.0f) ? x.x * __logf(rec) : 0.0f) - rec;
                    rec = acc[mi][nj][1];
                    lsum += ((x.y > 0.0f) ? x.y * __logf(rec) : 0.0f) - rec;
                }
                if (r + 8 < N_CELLS) {
                    float2 x = *(const float2*)(X + (size_t)(r + 8) * P_GENES + c);
                    float rec = acc[mi][nj][2];
                    lsum += ((x.x > 0.0f) ? x.x * __logf(rec) : 0.0f) - rec;
                    rec = acc[mi][nj][3];
                    lsum += ((x.y > 0.0f) ? x.y * __logf(rec) : 0.0f) - rec;
                }
            }
        }
    }
    double t = block_reduce512(lsum, tid);
    if (tid == 0) g_part1[blockIdx.y * gridDim.x + blockIdx.x] = t;
}

// ---- mat: M = B @ th^T, epilogue graph-prior logs (full grid) ----
__global__ void __launch_bounds__(512, 2)
mat_kernel(const float* __restrict__ adj,
           const float* __restrict__ kappa,
           const float* __restrict__ rho) {
    extern __shared__ char dsm[];
    int tid = threadIdx.x;
    int rowBase = blockIdx.y * 128;
    int colBase = blockIdx.x * 128;

    float acc[2][4][4];
    gemm_main(g_B_fr, blockIdx.y, g_th_fr, blockIdx.x, acc, dsm, tid);

    float sk = sigmoidf_(kappa[0]);
    float sr = sigmoidf_(rho[0]);
    float Af = (1.0f - sr) * (1.0f - sk);
    float C2 = (1.0f - sr) * sk;
    float C3 = Af + sr;

    int lane = tid & 31, warp = tid >> 5;
    int wm = warp >> 2, wn = warp & 3;
    int rq = lane >> 2, kp = (lane & 3) << 1;

    float lsum = 0.0f;
    #pragma unroll
    for (int mi = 0; mi < 2; mi++) {
        #pragma unroll
        for (int nj = 0; nj < 4; nj++) {
            int r0 = rowBase + wm * 32 + mi * 16 + rq;
            int c  = colBase + wn * 32 + nj * 8 + kp;
            if (c < P_GENES) {
                #pragma unroll
                for (int half = 0; half < 2; half++) {
                    int r = r0 + half * 8;
                    if (r < P_GENES) {
                        float2 a2 = *(const float2*)(adj + (size_t)r * P_GENES + c);
                        float m0 = acc[mi][nj][half * 2 + 0];
                        float m1 = acc[mi][nj][half * 2 + 1];
                        float arg0 = (a2.x > 0.5f) ? fmaf(Af, m0, C2) : fmaf(-Af, m0, C3);
                        float arg1 = (a2.y > 0.5f) ? fmaf(Af, m1, C2) : fmaf(-Af, m1, C3);
                        if (r != c)     lsum += __logf(arg0);
                        if (r != c + 1) lsum += __logf(arg1);
                    }
                }
            }
        }
    }
    double t = block_reduce512(lsum, tid);
    if (tid == 0) g_part2[blockIdx.y * gridDim.x + blockIdx.x] = t;
}

// ---------------- final reduction ----------------
__global__ void __launch_bounds__(256)
fin_kernel(float* out) {
    int tid = threadIdx.x;
    double s1 = 0.0, s2 = 0.0;
    for (int i = tid; i < NPART1; i += 256) s1 += g_part1[i];
    for (int i = tid; i < NPART2; i += 256) s2 += g_part2[i];
    #pragma unroll
    for (int off = 16; off > 0; off >>= 1) {
        s1 += __shfl_xor_sync(0xffffffff, s1, off);
        s2 += __shfl_xor_sync(0xffffffff, s2, off);
    }
    __shared__ double r1[8], r2[8];
    if ((tid & 31) == 0) { r1[tid >> 5] = s1; r2[tid >> 5] = s2; }
    __syncthreads();
    if (tid == 0) {
        double t1 = 0.0, t2 = 0.0;
        #pragma unroll
        for (int w = 0; w < 8; w++) { t1 += r1[w]; t2 += r2[w]; }
        out[0] = (float)(-(LAM_D * t1 + t2));
    }
}

// ---------------- launch ----------------
extern "C" void kernel_launch(void* const* d_in, const int* in_sizes, int n_in,
                              void* d_out, int out_size) {
    const float* X     = (const float*)d_in[0];
    const float* adj   = (const float*)d_in[1];
    // d_in[2] adj_1m, d_in[3] weights: derivable from binary adj, unused
    const float* theta = (const float*)d_in[4];
    const float* alpha = (const float*)d_in[5];
    const float* eta   = (const float*)d_in[6];
    const float* gs    = (const float*)d_in[7];
    const float* kappa = (const float*)d_in[8];
    const float* rho   = (const float*)d_in[9];
    float* out = (float*)d_out;

    cudaFuncSetAttribute(recon_kernel, cudaFuncAttributeMaxDynamicSharedMemorySize, FRAG_SMEM);
    cudaFuncSetAttribute(mat_kernel,   cudaFuncAttributeMaxDynamicSharedMemorySize, FRAG_SMEM);

    // fork s2 off capture stream
    cudaEventRecord(g_evStart, 0);
    cudaStreamWaitEvent(g_s2, g_evStart, 0);

    // s2: a = exp(alpha)
    expa_kernel<<<(N_PADR * 56 + 255) / 256, 256, 0, g_s2>>>(alpha);
    cudaEventRecord(g_evA, g_s2);

    // s0: et -> theta
    et_kernel<<<(L_FAC * L_FAC + 255) / 256, 256>>>(eta);
    theta_kernel<<<P_GENES / 16, 256>>>(theta, gs);
    cudaEventRecord(g_evTh, 0);

    // s2: mat (needs theta outputs only)
    cudaStreamWaitEvent(g_s2, g_evTh, 0);
    dim3 gMat(GRID_X, GRID_X);
    mat_kernel<<<gMat, 512, FRAG_SMEM, g_s2>>>(adj, kappa, rho);
    cudaEventRecord(g_evM, g_s2);

    // s0: recon (needs g_a and theta outputs)
    cudaStreamWaitEvent(0, g_evA, 0);
    dim3 gRecon(GRID_X, GRID_Y1);
    recon_kernel<<<gRecon, 512, FRAG_SMEM>>>(X);

    // join
    cudaStreamWaitEvent(0, g_evM, 0);
    fin_kernel<<<1, 256>>>(out);
}